// round 5
// baseline (speedup 1.0000x reference)
#include <cuda_runtime.h>
#include <cuda_bf16.h>
#include <cstdint>

// ---------------------------------------------------------------------------
// GraphSAGE 2-layer backbone, CSR gather-reduce + f32x2 packed dense.
// Inputs: x[N,64] f32, edge_index[2,E] int32, W1_l[128,64], b1[128],
//         W1_r[128,64], W2_l[128,128], b2[128], W2_r[128,128]
// Output: [N,128] f32
// ---------------------------------------------------------------------------

static constexpr int NN   = 100000;
static constexpr int EE   = 1600000;
static constexpr int F_IN = 64;
static constexpr int F_H  = 128;

__device__ __align__(16) float g_agg1 [(size_t)NN * F_IN];
__device__ __align__(16) float g_h    [(size_t)NN * F_H];
__device__ __align__(16) float g_agg2 [(size_t)NN * F_H];
__device__ __align__(16) float g_dinv [NN];
__device__ __align__(16) int   g_degi [NN];
__device__ __align__(16) int   g_rowp [NN + 1];
__device__ __align__(16) int   g_curs [NN];
__device__ __align__(16) int   g_csr  [EE];
__device__ __align__(16) float g_w1t  [2 * F_IN * 128];
__device__ __align__(16) float g_w2t  [2 * F_H  * 128];

// ---------------------------------------------------------------------------
// f32x2 packed helpers (ptxas never emits FFMA2 from C++ — PTX only)
__device__ __forceinline__ unsigned long long pk2(float a, float b) {
    unsigned long long r;
    asm("mov.b64 %0, {%1, %2};" : "=l"(r) : "f"(a), "f"(b));
    return r;
}
__device__ __forceinline__ void fma2(unsigned long long& d,
                                     unsigned long long a,
                                     unsigned long long b) {
    asm("fma.rn.f32x2 %0, %1, %2, %0;" : "+l"(d) : "l"(a), "l"(b));
}
__device__ __forceinline__ float2 upk2(unsigned long long v) {
    float2 f;
    asm("mov.b64 {%0, %1}, %2;" : "=f"(f.x), "=f"(f.y) : "l"(v));
    return f;
}

// ---------------------------------------------------------------------------
__global__ void zero_int_kernel(int* p, int n) {
    int i = blockIdx.x * blockDim.x + threadIdx.x;
    if (i < n) p[i] = 0;
}

template <int K>
__global__ void pack_kernel(const float* __restrict__ Wl,
                            const float* __restrict__ Wr,
                            float* __restrict__ WcT) {
    int i = blockIdx.x * blockDim.x + threadIdx.x;
    if (i >= 2 * K * 128) return;
    int k = i >> 7;
    int j = i & 127;
    WcT[i] = (k < K) ? Wl[j * K + k] : Wr[j * K + (k - K)];
}

__global__ void hist_kernel(const int* __restrict__ ei, int E, int nnodes,
                            int* __restrict__ degi) {
    int e = blockIdx.x * blockDim.x + threadIdx.x;
    if (e >= E) return;
    int dst = __ldg(&ei[E + e]);
    if ((unsigned)dst < (unsigned)nnodes) atomicAdd(&degi[dst], 1);
}

__global__ void scan_kernel(const int* __restrict__ degi,
                            int* __restrict__ rowp,
                            int* __restrict__ curs,
                            float* __restrict__ dinv,
                            int n, int E) {
    __shared__ int ssum[1024];
    const int t = threadIdx.x;
    const int ITEMS = (n + 1023) / 1024;
    const int beg = t * ITEMS;
    const int end = min(beg + ITEMS, n);

    int s = 0;
    for (int i = beg; i < end; i++) s += degi[i];
    ssum[t] = s;
    __syncthreads();
    for (int off = 1; off < 1024; off <<= 1) {
        int v = (t >= off) ? ssum[t - off] : 0;
        __syncthreads();
        ssum[t] += v;
        __syncthreads();
    }
    int run = (t == 0) ? 0 : ssum[t - 1];
    for (int i = beg; i < end; i++) {
        int d = degi[i];
        rowp[i] = run;
        curs[i] = run;
        dinv[i] = 1.0f / fmaxf((float)d, 1.0f);
        run += d;
    }
    if (t == 1023) rowp[n] = ssum[1023];
}

__global__ void scatter_kernel(const int* __restrict__ ei, int E, int nnodes,
                               int* __restrict__ curs,
                               int* __restrict__ csr) {
    int e = blockIdx.x * blockDim.x + threadIdx.x;
    if (e >= E) return;
    int src = __ldg(&ei[e]);
    int dst = __ldg(&ei[E + e]);
    if ((unsigned)src >= (unsigned)nnodes || (unsigned)dst >= (unsigned)nnodes) return;
    int pos = atomicAdd(&curs[dst], 1);
    csr[pos] = src;
}

// Gather-reduce mean aggregation, 4-way unroll (front-batched LDGs, MLP=4).
template <int F4>
__global__ void gather_agg_kernel(const float4* __restrict__ in4,
                                  const int* __restrict__ rowp,
                                  const int* __restrict__ csr,
                                  const float* __restrict__ dinv,
                                  float4* __restrict__ aggout,
                                  int n) {
    constexpr int GPB = 256 / F4;
    const int node = blockIdx.x * GPB + (threadIdx.x / F4);
    const int lane = threadIdx.x & (F4 - 1);
    if (node >= n) return;

    const int beg = __ldg(&rowp[node]);
    const int end = __ldg(&rowp[node + 1]);

    float4 a0 = make_float4(0.f, 0.f, 0.f, 0.f);
    float4 a1 = make_float4(0.f, 0.f, 0.f, 0.f);
    float4 a2 = make_float4(0.f, 0.f, 0.f, 0.f);
    float4 a3 = make_float4(0.f, 0.f, 0.f, 0.f);

    int j = beg;
    for (; j + 4 <= end; j += 4) {
        int s0 = __ldg(&csr[j]);
        int s1 = __ldg(&csr[j + 1]);
        int s2 = __ldg(&csr[j + 2]);
        int s3 = __ldg(&csr[j + 3]);
        float4 v0 = __ldg(&in4[(size_t)s0 * F4 + lane]);
        float4 v1 = __ldg(&in4[(size_t)s1 * F4 + lane]);
        float4 v2 = __ldg(&in4[(size_t)s2 * F4 + lane]);
        float4 v3 = __ldg(&in4[(size_t)s3 * F4 + lane]);
        a0.x += v0.x; a0.y += v0.y; a0.z += v0.z; a0.w += v0.w;
        a1.x += v1.x; a1.y += v1.y; a1.z += v1.z; a1.w += v1.w;
        a2.x += v2.x; a2.y += v2.y; a2.z += v2.z; a2.w += v2.w;
        a3.x += v3.x; a3.y += v3.y; a3.z += v3.z; a3.w += v3.w;
    }
    for (; j < end; j++) {
        int s0 = __ldg(&csr[j]);
        float4 v0 = __ldg(&in4[(size_t)s0 * F4 + lane]);
        a0.x += v0.x; a0.y += v0.y; a0.z += v0.z; a0.w += v0.w;
    }

    const float di = __ldg(&dinv[node]);
    float4 r;
    r.x = (a0.x + a1.x + a2.x + a3.x) * di;
    r.y = (a0.y + a1.y + a2.y + a3.y) * di;
    r.z = (a0.z + a1.z + a2.z + a3.z) * di;
    r.w = (a0.w + a1.w + a2.w + a3.w) * di;
    aggout[(size_t)node * F4 + lane] = r;
}

// Fused dense layer with f32x2 packed accumulation.
// out[n][j] = act( sum_k cat(agg, x)[n][k] * WcT[k][j] + b[j] )
// blockDim=256 (8 warps). Tile = 64 nodes; warp: 8 nodes; lane: 4 j's (2 packs).
template <int K, bool RELU>
__global__ void __launch_bounds__(256)
dense_kernel(const float* __restrict__ xin,
             const float* __restrict__ agg,
             const float* __restrict__ WcT,
             const float* __restrict__ bias,
             float* __restrict__ out,
             int nnodes) {
    constexpr int K2 = 2 * K;
    extern __shared__ float sm[];
    float* sW = sm;                 // K2*128, layout [k][j]
    float* sC = sm + K2 * 128;      // 64 nodes * K2, layout [n][k]
    __shared__ float sB[128];

    const int tid  = threadIdx.x;
    const int base = blockIdx.x * 64;

    if (tid < 128) sB[tid] = bias[tid];
    for (int i = tid; i < K2 * 128; i += 256) sW[i] = WcT[i];

    for (int i = tid; i < 64 * K; i += 256) {
        int n = i / K;
        int k = i - n * K;
        int node = base + n;
        float xv = 0.f, av = 0.f;
        if (node < nnodes) {
            size_t off = (size_t)node * K + k;
            xv = xin[off];
            av = agg[off];
        }
        sC[n * K2 + k]     = av;
        sC[n * K2 + K + k] = xv;
    }
    __syncthreads();

    const int w = tid >> 5;
    const int l = tid & 31;

    unsigned long long acc01[8], acc23[8];
    {
        unsigned long long b01 = pk2(sB[4 * l], sB[4 * l + 1]);
        unsigned long long b23 = pk2(sB[4 * l + 2], sB[4 * l + 3]);
#pragma unroll
        for (int m = 0; m < 8; m++) { acc01[m] = b01; acc23[m] = b23; }
    }

    const float4* sW4 = reinterpret_cast<const float4*>(sW);
    const float*  sCw = sC + (w * 8) * K2;

#pragma unroll 4
    for (int k = 0; k < K2; k++) {
        float4 wv = sW4[k * 32 + l];                  // conflict-free LDS.128
        unsigned long long w01 = pk2(wv.x, wv.y);
        unsigned long long w23 = pk2(wv.z, wv.w);
#pragma unroll
        for (int m = 0; m < 8; m++) {
            float c = sCw[m * K2 + k];                // broadcast LDS
            unsigned long long c2 = pk2(c, c);
            fma2(acc01[m], c2, w01);
            fma2(acc23[m], c2, w23);
        }
    }

#pragma unroll
    for (int m = 0; m < 8; m++) {
        int node = base + w * 8 + m;
        if (node >= nnodes) continue;
        float2 p01 = upk2(acc01[m]);
        float2 p23 = upk2(acc23[m]);
        float4 o;
        o.x = p01.x; o.y = p01.y; o.z = p23.x; o.w = p23.y;
        if (RELU) {
            o.x = fmaxf(o.x, 0.f); o.y = fmaxf(o.y, 0.f);
            o.z = fmaxf(o.z, 0.f); o.w = fmaxf(o.w, 0.f);
        }
        reinterpret_cast<float4*>(out)[(size_t)node * 32 + l] = o;
    }
}

// ---------------------------------------------------------------------------
extern "C" void kernel_launch(void* const* d_in, const int* in_sizes, int n_in,
                              void* d_out, int out_size) {
    const float* x    = (const float*)d_in[0];
    const int*   ei   = (const int*)d_in[1];
    const float* W1_l = (const float*)d_in[2];
    const float* b1   = (const float*)d_in[3];
    const float* W1_r = (const float*)d_in[4];
    const float* W2_l = (const float*)d_in[5];
    const float* b2   = (const float*)d_in[6];
    const float* W2_r = (const float*)d_in[7];
    float*       out  = (float*)d_out;

    const int n = in_sizes[0] / F_IN;   // 100000
    const int E = in_sizes[1] / 2;      // 1600000

    void *p_agg1, *p_h, *p_agg2, *p_dinv, *p_degi, *p_rowp, *p_curs, *p_csr,
         *p_w1t, *p_w2t;
    cudaGetSymbolAddress(&p_agg1, g_agg1);
    cudaGetSymbolAddress(&p_h,    g_h);
    cudaGetSymbolAddress(&p_agg2, g_agg2);
    cudaGetSymbolAddress(&p_dinv, g_dinv);
    cudaGetSymbolAddress(&p_degi, g_degi);
    cudaGetSymbolAddress(&p_rowp, g_rowp);
    cudaGetSymbolAddress(&p_curs, g_curs);
    cudaGetSymbolAddress(&p_csr,  g_csr);
    cudaGetSymbolAddress(&p_w1t,  g_w1t);
    cudaGetSymbolAddress(&p_w2t,  g_w2t);
    float* agg1 = (float*)p_agg1;
    float* h    = (float*)p_h;
    float* agg2 = (float*)p_agg2;
    float* dinv = (float*)p_dinv;
    int*   degi = (int*)p_degi;
    int*   rowp = (int*)p_rowp;
    int*   curs = (int*)p_curs;
    int*   csr  = (int*)p_csr;
    float* w1t  = (float*)p_w1t;
    float* w2t  = (float*)p_w2t;

    const int smem1 = (2 * F_IN * 128 + 64 * 2 * F_IN) * (int)sizeof(float); //  96KB
    const int smem2 = (2 * F_H  * 128 + 64 * 2 * F_H ) * (int)sizeof(float); // 192KB
    cudaFuncSetAttribute(dense_kernel<F_IN, true>,
                         cudaFuncAttributeMaxDynamicSharedMemorySize, smem1);
    cudaFuncSetAttribute(dense_kernel<F_H, false>,
                         cudaFuncAttributeMaxDynamicSharedMemorySize, smem2);

    // weight packing
    pack_kernel<F_IN><<<(2 * F_IN * 128 + 255) / 256, 256>>>(W1_l, W1_r, w1t);
    pack_kernel<F_H ><<<(2 * F_H  * 128 + 255) / 256, 256>>>(W2_l, W2_r, w2t);

    // CSR build
    zero_int_kernel<<<(n + 255) / 256, 256>>>(degi, n);
    hist_kernel<<<(E + 255) / 256, 256>>>(ei, E, n, degi);
    scan_kernel<<<1, 1024>>>(degi, rowp, curs, dinv, n, E);
    scatter_kernel<<<(E + 255) / 256, 256>>>(ei, E, n, curs, csr);

    // layer 1
    gather_agg_kernel<F_IN / 4><<<(n * (F_IN / 4) + 255) / 256, 256>>>(
        (const float4*)x, rowp, csr, dinv, (float4*)agg1, n);
    dense_kernel<F_IN, true><<<(n + 63) / 64, 256, smem1>>>(
        x, agg1, w1t, b1, h, n);

    // layer 2
    gather_agg_kernel<F_H / 4><<<(n * (F_H / 4) + 255) / 256, 256>>>(
        (const float4*)h, rowp, csr, dinv, (float4*)agg2, n);
    dense_kernel<F_H, false><<<(n + 63) / 64, 256, smem2>>>(
        h, agg2, w2t, b2, out, n);
}

// round 6
// speedup vs baseline: 1.1069x; 1.1069x over previous
#include <cuda_runtime.h>
#include <cuda_bf16.h>
#include <cstdint>

// ---------------------------------------------------------------------------
// GraphSAGE 2-layer backbone, CSR gather-reduce + f32x2 packed dense.
// Launch order chosen so ncu (-s..-c1 => slot #4) profiles gather1.
// Inputs: x[N,64] f32, edge_index[2,E] int32, W1_l[128,64], b1[128],
//         W1_r[128,64], W2_l[128,128], b2[128], W2_r[128,128]
// Output: [N,128] f32
// ---------------------------------------------------------------------------

static constexpr int NN   = 100000;
static constexpr int EE   = 1600000;
static constexpr int F_IN = 64;
static constexpr int F_H  = 128;

__device__ __align__(16) float g_agg1 [(size_t)NN * F_IN];
__device__ __align__(16) float g_h    [(size_t)NN * F_H];
__device__ __align__(16) float g_agg2 [(size_t)NN * F_H];
__device__ __align__(16) float g_dinv [NN];
__device__ __align__(16) int   g_degi [NN];      // zero at load; scan re-zeroes
__device__ __align__(16) int   g_rowp [NN + 1];
__device__ __align__(16) int   g_curs [NN];
__device__ __align__(16) int   g_csr  [EE];
__device__ __align__(16) float g_w1t  [2 * F_IN * 128];
__device__ __align__(16) float g_w2t  [2 * F_H  * 128];

// ---------------------------------------------------------------------------
__device__ __forceinline__ unsigned long long pk2(float a, float b) {
    unsigned long long r;
    asm("mov.b64 %0, {%1, %2};" : "=l"(r) : "f"(a), "f"(b));
    return r;
}
__device__ __forceinline__ void fma2(unsigned long long& d,
                                     unsigned long long a,
                                     unsigned long long b) {
    asm("fma.rn.f32x2 %0, %1, %2, %0;" : "+l"(d) : "l"(a), "l"(b));
}
__device__ __forceinline__ float2 upk2(unsigned long long v) {
    float2 f;
    asm("mov.b64 {%0, %1}, %2;" : "=f"(f.x), "=f"(f.y) : "l"(v));
    return f;
}

// ---------------------------------------------------------------------------
// Pack BOTH layers' weights in one launch. WcT[k*128+j].
__global__ void pack_all_kernel(const float* __restrict__ W1l,
                                const float* __restrict__ W1r,
                                const float* __restrict__ W2l,
                                const float* __restrict__ W2r,
                                float* __restrict__ w1t,
                                float* __restrict__ w2t) {
    int i = blockIdx.x * blockDim.x + threadIdx.x;
    // layer1: 2*64*128 = 16384
    if (i < 2 * F_IN * 128) {
        int k = i >> 7, j = i & 127;
        w1t[i] = (k < F_IN) ? W1l[j * F_IN + k] : W1r[j * F_IN + (k - F_IN)];
    }
    // layer2: 2*128*128 = 32768
    if (i < 2 * F_H * 128) {
        int k = i >> 7, j = i & 127;
        w2t[i] = (k < F_H) ? W2l[j * F_H + k] : W2r[j * F_H + (k - F_H)];
    }
}

__global__ void hist_kernel(const int* __restrict__ ei, int E, int nnodes,
                            int* __restrict__ degi) {
    int e = blockIdx.x * blockDim.x + threadIdx.x;
    if (e >= E) return;
    int dst = __ldg(&ei[E + e]);
    if ((unsigned)dst < (unsigned)nnodes) atomicAdd(&degi[dst], 1);
}

// Exclusive scan; also re-zeroes degi so the next run's hist starts clean
// (device globals are zero-initialized at module load => run-invariant).
__global__ void scan_kernel(int* __restrict__ degi,
                            int* __restrict__ rowp,
                            int* __restrict__ curs,
                            float* __restrict__ dinv,
                            int n) {
    __shared__ int ssum[1024];
    const int t = threadIdx.x;
    const int ITEMS = (n + 1023) / 1024;
    const int beg = t * ITEMS;
    const int end = min(beg + ITEMS, n);

    int s = 0;
    for (int i = beg; i < end; i++) s += degi[i];
    ssum[t] = s;
    __syncthreads();
    for (int off = 1; off < 1024; off <<= 1) {
        int v = (t >= off) ? ssum[t - off] : 0;
        __syncthreads();
        ssum[t] += v;
        __syncthreads();
    }
    int run = (t == 0) ? 0 : ssum[t - 1];
    for (int i = beg; i < end; i++) {
        int d = degi[i];
        degi[i] = 0;                       // reset for next run
        rowp[i] = run;
        curs[i] = run;
        dinv[i] = 1.0f / fmaxf((float)d, 1.0f);
        run += d;
    }
    if (t == 1023) rowp[n] = ssum[1023];
}

__global__ void scatter_kernel(const int* __restrict__ ei, int E, int nnodes,
                               int* __restrict__ curs,
                               int* __restrict__ csr) {
    int e = blockIdx.x * blockDim.x + threadIdx.x;
    if (e >= E) return;
    int src = __ldg(&ei[e]);
    int dst = __ldg(&ei[E + e]);
    if ((unsigned)src >= (unsigned)nnodes || (unsigned)dst >= (unsigned)nnodes) return;
    int pos = atomicAdd(&curs[dst], 1);
    csr[pos] = src;
}

// Gather-reduce mean aggregation, 4-way unroll (front-batched LDGs, MLP=4).
template <int F4>
__global__ void gather_agg_kernel(const float4* __restrict__ in4,
                                  const int* __restrict__ rowp,
                                  const int* __restrict__ csr,
                                  const float* __restrict__ dinv,
                                  float4* __restrict__ aggout,
                                  int n) {
    constexpr int GPB = 256 / F4;
    const int node = blockIdx.x * GPB + (threadIdx.x / F4);
    const int lane = threadIdx.x & (F4 - 1);
    if (node >= n) return;

    const int beg = __ldg(&rowp[node]);
    const int end = __ldg(&rowp[node + 1]);

    float4 a0 = make_float4(0.f, 0.f, 0.f, 0.f);
    float4 a1 = make_float4(0.f, 0.f, 0.f, 0.f);
    float4 a2 = make_float4(0.f, 0.f, 0.f, 0.f);
    float4 a3 = make_float4(0.f, 0.f, 0.f, 0.f);

    int j = beg;
    for (; j + 4 <= end; j += 4) {
        int s0 = __ldg(&csr[j]);
        int s1 = __ldg(&csr[j + 1]);
        int s2 = __ldg(&csr[j + 2]);
        int s3 = __ldg(&csr[j + 3]);
        float4 v0 = __ldg(&in4[(size_t)s0 * F4 + lane]);
        float4 v1 = __ldg(&in4[(size_t)s1 * F4 + lane]);
        float4 v2 = __ldg(&in4[(size_t)s2 * F4 + lane]);
        float4 v3 = __ldg(&in4[(size_t)s3 * F4 + lane]);
        a0.x += v0.x; a0.y += v0.y; a0.z += v0.z; a0.w += v0.w;
        a1.x += v1.x; a1.y += v1.y; a1.z += v1.z; a1.w += v1.w;
        a2.x += v2.x; a2.y += v2.y; a2.z += v2.z; a2.w += v2.w;
        a3.x += v3.x; a3.y += v3.y; a3.z += v3.z; a3.w += v3.w;
    }
    for (; j < end; j++) {
        int s0 = __ldg(&csr[j]);
        float4 v0 = __ldg(&in4[(size_t)s0 * F4 + lane]);
        a0.x += v0.x; a0.y += v0.y; a0.z += v0.z; a0.w += v0.w;
    }

    const float di = __ldg(&dinv[node]);
    float4 r;
    r.x = (a0.x + a1.x + a2.x + a3.x) * di;
    r.y = (a0.y + a1.y + a2.y + a3.y) * di;
    r.z = (a0.z + a1.z + a2.z + a3.z) * di;
    r.w = (a0.w + a1.w + a2.w + a3.w) * di;
    aggout[(size_t)node * F4 + lane] = r;
}

// Fused dense layer, f32x2 accumulators, float4 activation reads (k-step-4).
template <int K, bool RELU>
__global__ void __launch_bounds__(256)
dense_kernel(const float* __restrict__ xin,
             const float* __restrict__ agg,
             const float* __restrict__ WcT,
             const float* __restrict__ bias,
             float* __restrict__ out,
             int nnodes) {
    constexpr int K2 = 2 * K;
    extern __shared__ float sm[];
    float* sW = sm;                 // K2*128, layout [k][j]
    float* sC = sm + K2 * 128;      // 64 nodes * K2, layout [n][k]
    __shared__ float sB[128];

    const int tid  = threadIdx.x;
    const int base = blockIdx.x * 64;

    if (tid < 128) sB[tid] = bias[tid];
    {   // weights, float4 staging
        float4*       dst4 = reinterpret_cast<float4*>(sW);
        const float4* src4 = reinterpret_cast<const float4*>(WcT);
        for (int i = tid; i < K2 * 32; i += 256) dst4[i] = src4[i];
    }
    {   // concat tile, float4 staging
        constexpr int KQ = K / 4;
        const float4* x4 = reinterpret_cast<const float4*>(xin);
        const float4* a4 = reinterpret_cast<const float4*>(agg);
        float4 z = make_float4(0.f, 0.f, 0.f, 0.f);
        for (int i = tid; i < 64 * KQ; i += 256) {
            int n  = i / KQ;
            int kq = i - n * KQ;
            int node = base + n;
            float4 xv = z, av = z;
            if (node < nnodes) {
                size_t off = (size_t)node * KQ + kq;
                xv = x4[off];
                av = a4[off];
            }
            reinterpret_cast<float4*>(sC + n * K2)[kq]          = av;
            reinterpret_cast<float4*>(sC + n * K2 + K)[kq]      = xv;
        }
    }
    __syncthreads();

    const int w = tid >> 5;
    const int l = tid & 31;

    unsigned long long acc01[8], acc23[8];
    {
        unsigned long long b01 = pk2(sB[4 * l], sB[4 * l + 1]);
        unsigned long long b23 = pk2(sB[4 * l + 2], sB[4 * l + 3]);
#pragma unroll
        for (int m = 0; m < 8; m++) { acc01[m] = b01; acc23[m] = b23; }
    }

    const float4* sW4 = reinterpret_cast<const float4*>(sW);
    const float4* sC4 = reinterpret_cast<const float4*>(sC + (w * 8) * K2);

#pragma unroll 2
    for (int k4 = 0; k4 < K2 / 4; k4++) {
        unsigned long long wp[4][2];
#pragma unroll
        for (int kk = 0; kk < 4; kk++) {
            float4 wv = sW4[(4 * k4 + kk) * 32 + l];   // conflict-free LDS.128
            wp[kk][0] = pk2(wv.x, wv.y);
            wp[kk][1] = pk2(wv.z, wv.w);
        }
#pragma unroll
        for (int m = 0; m < 8; m++) {
            float4 c4 = sC4[m * (K2 / 4) + k4];        // broadcast LDS.128
            unsigned long long cc;
            cc = pk2(c4.x, c4.x); fma2(acc01[m], cc, wp[0][0]); fma2(acc23[m], cc, wp[0][1]);
            cc = pk2(c4.y, c4.y); fma2(acc01[m], cc, wp[1][0]); fma2(acc23[m], cc, wp[1][1]);
            cc = pk2(c4.z, c4.z); fma2(acc01[m], cc, wp[2][0]); fma2(acc23[m], cc, wp[2][1]);
            cc = pk2(c4.w, c4.w); fma2(acc01[m], cc, wp[3][0]); fma2(acc23[m], cc, wp[3][1]);
        }
    }

#pragma unroll
    for (int m = 0; m < 8; m++) {
        int node = base + w * 8 + m;
        if (node >= nnodes) continue;
        float2 p01 = upk2(acc01[m]);
        float2 p23 = upk2(acc23[m]);
        float4 o;
        o.x = p01.x; o.y = p01.y; o.z = p23.x; o.w = p23.y;
        if (RELU) {
            o.x = fmaxf(o.x, 0.f); o.y = fmaxf(o.y, 0.f);
            o.z = fmaxf(o.z, 0.f); o.w = fmaxf(o.w, 0.f);
        }
        reinterpret_cast<float4*>(out)[(size_t)node * 32 + l] = o;
    }
}

// ---------------------------------------------------------------------------
extern "C" void kernel_launch(void* const* d_in, const int* in_sizes, int n_in,
                              void* d_out, int out_size) {
    const float* x    = (const float*)d_in[0];
    const int*   ei   = (const int*)d_in[1];
    const float* W1_l = (const float*)d_in[2];
    const float* b1   = (const float*)d_in[3];
    const float* W1_r = (const float*)d_in[4];
    const float* W2_l = (const float*)d_in[5];
    const float* b2   = (const float*)d_in[6];
    const float* W2_r = (const float*)d_in[7];
    float*       out  = (float*)d_out;

    const int n = in_sizes[0] / F_IN;   // 100000
    const int E = in_sizes[1] / 2;      // 1600000

    void *p_agg1, *p_h, *p_agg2, *p_dinv, *p_degi, *p_rowp, *p_curs, *p_csr,
         *p_w1t, *p_w2t;
    cudaGetSymbolAddress(&p_agg1, g_agg1);
    cudaGetSymbolAddress(&p_h,    g_h);
    cudaGetSymbolAddress(&p_agg2, g_agg2);
    cudaGetSymbolAddress(&p_dinv, g_dinv);
    cudaGetSymbolAddress(&p_degi, g_degi);
    cudaGetSymbolAddress(&p_rowp, g_rowp);
    cudaGetSymbolAddress(&p_curs, g_curs);
    cudaGetSymbolAddress(&p_csr,  g_csr);
    cudaGetSymbolAddress(&p_w1t,  g_w1t);
    cudaGetSymbolAddress(&p_w2t,  g_w2t);
    float* agg1 = (float*)p_agg1;
    float* h    = (float*)p_h;
    float* agg2 = (float*)p_agg2;
    float* dinv = (float*)p_dinv;
    int*   degi = (int*)p_degi;
    int*   rowp = (int*)p_rowp;
    int*   curs = (int*)p_curs;
    int*   csr  = (int*)p_csr;
    float* w1t  = (float*)p_w1t;
    float* w2t  = (float*)p_w2t;

    const int smem1 = (2 * F_IN * 128 + 64 * 2 * F_IN) * (int)sizeof(float); //  96KB
    const int smem2 = (2 * F_H  * 128 + 64 * 2 * F_H ) * (int)sizeof(float); // 192KB
    cudaFuncSetAttribute(dense_kernel<F_IN, true>,
                         cudaFuncAttributeMaxDynamicSharedMemorySize, smem1);
    cudaFuncSetAttribute(dense_kernel<F_H, false>,
                         cudaFuncAttributeMaxDynamicSharedMemorySize, smem2);

    // #1 hist (degi is zero: zero-init at load, re-zeroed by scan each run)
    hist_kernel<<<(E + 255) / 256, 256>>>(ei, E, n, degi);
    // #2 scan (+ degi reset)
    scan_kernel<<<1, 1024>>>(degi, rowp, curs, dinv, n);
    // #3 counting-sort scatter
    scatter_kernel<<<(E + 255) / 256, 256>>>(ei, E, n, curs, csr);
    // #4 gather1  <-- ncu profiles this slot
    gather_agg_kernel<F_IN / 4><<<(n * (F_IN / 4) + 255) / 256, 256>>>(
        (const float4*)x, rowp, csr, dinv, (float4*)agg1, n);
    // #5 weight packing (both layers)
    pack_all_kernel<<<(2 * F_H * 128 + 255) / 256, 256>>>(
        W1_l, W1_r, W2_l, W2_r, w1t, w2t);
    // #6 dense1 + relu -> h
    dense_kernel<F_IN, true><<<(n + 63) / 64, 256, smem1>>>(
        x, agg1, w1t, b1, h, n);
    // #7 gather2
    gather_agg_kernel<F_H / 4><<<(n * (F_H / 4) + 255) / 256, 256>>>(
        (const float4*)h, rowp, csr, dinv, (float4*)agg2, n);
    // #8 dense2 -> out
    dense_kernel<F_H, false><<<(n + 63) / 64, 256, smem2>>>(
        h, agg2, w2t, b2, out, n);
}

// round 7
// speedup vs baseline: 1.7254x; 1.5589x over previous
#include <cuda_runtime.h>
#include <cuda_bf16.h>
#include <cstdint>

// ---------------------------------------------------------------------------
// GraphSAGE 2-layer backbone, CSR gather-reduce + f32x2 packed dense.
// R7: multi-block coalesced CSR scan (old single-block scan was ~350us!).
// Inputs: x[N,64] f32, edge_index[2,E] int32, W1_l[128,64], b1[128],
//         W1_r[128,64], W2_l[128,128], b2[128], W2_r[128,128]
// Output: [N,128] f32
// ---------------------------------------------------------------------------

static constexpr int NN   = 100000;
static constexpr int EE   = 1600000;
static constexpr int F_IN = 64;
static constexpr int F_H  = 128;
static constexpr int SCAN_CHUNK = 512;
static constexpr int SCAN_NBLK  = (NN + SCAN_CHUNK - 1) / SCAN_CHUNK;  // 196

__device__ __align__(16) float g_agg1 [(size_t)NN * F_IN];
__device__ __align__(16) float g_h    [(size_t)NN * F_H];
__device__ __align__(16) float g_agg2 [(size_t)NN * F_H];
__device__ __align__(16) float g_dinv [NN];
__device__ __align__(16) int   g_degi [NN];      // zero at load; final re-zeroes
__device__ __align__(16) int   g_rowp [NN + 1];
__device__ __align__(16) int   g_curs [NN];
__device__ __align__(16) int   g_csr  [EE];
__device__ __align__(16) int   g_bsum [256];
__device__ __align__(16) int   g_boff [256];
__device__ __align__(16) float g_w1t  [2 * F_IN * 128];
__device__ __align__(16) float g_w2t  [2 * F_H  * 128];

// ---------------------------------------------------------------------------
__device__ __forceinline__ unsigned long long pk2(float a, float b) {
    unsigned long long r;
    asm("mov.b64 %0, {%1, %2};" : "=l"(r) : "f"(a), "f"(b));
    return r;
}
__device__ __forceinline__ void fma2(unsigned long long& d,
                                     unsigned long long a,
                                     unsigned long long b) {
    asm("fma.rn.f32x2 %0, %1, %2, %0;" : "+l"(d) : "l"(a), "l"(b));
}
__device__ __forceinline__ float2 upk2(unsigned long long v) {
    float2 f;
    asm("mov.b64 {%0, %1}, %2;" : "=f"(f.x), "=f"(f.y) : "l"(v));
    return f;
}

// ---------------------------------------------------------------------------
__global__ void pack_all_kernel(const float* __restrict__ W1l,
                                const float* __restrict__ W1r,
                                const float* __restrict__ W2l,
                                const float* __restrict__ W2r,
                                float* __restrict__ w1t,
                                float* __restrict__ w2t) {
    int i = blockIdx.x * blockDim.x + threadIdx.x;
    if (i < 2 * F_IN * 128) {
        int k = i >> 7, j = i & 127;
        w1t[i] = (k < F_IN) ? W1l[j * F_IN + k] : W1r[j * F_IN + (k - F_IN)];
    }
    if (i < 2 * F_H * 128) {
        int k = i >> 7, j = i & 127;
        w2t[i] = (k < F_H) ? W2l[j * F_H + k] : W2r[j * F_H + (k - F_H)];
    }
}

__global__ void hist_kernel(const int* __restrict__ ei, int E, int nnodes,
                            int* __restrict__ degi) {
    int e = blockIdx.x * blockDim.x + threadIdx.x;
    if (e >= E) return;
    int dst = __ldg(&ei[E + e]);
    if ((unsigned)dst < (unsigned)nnodes) atomicAdd(&degi[dst], 1);
}

// ---- coalesced 3-pass exclusive scan over degi ----
__global__ void scan_partial_kernel(const int* __restrict__ degi,
                                    int* __restrict__ bsum, int n) {
    __shared__ int s[SCAN_CHUNK];
    int t = threadIdx.x;
    int i = blockIdx.x * SCAN_CHUNK + t;
    s[t] = (i < n) ? degi[i] : 0;
    __syncthreads();
    for (int off = SCAN_CHUNK / 2; off > 0; off >>= 1) {
        if (t < off) s[t] += s[t + off];
        __syncthreads();
    }
    if (t == 0) bsum[blockIdx.x] = s[0];
}

__global__ void scan_bsum_kernel(const int* __restrict__ bsum,
                                 int* __restrict__ boff,
                                 int* __restrict__ rowp,
                                 int nblk, int n) {
    __shared__ int s[256];
    int t = threadIdx.x;
    s[t] = (t < nblk) ? bsum[t] : 0;
    __syncthreads();
    for (int off = 1; off < 256; off <<= 1) {
        int v = (t >= off) ? s[t - off] : 0;
        __syncthreads();
        s[t] += v;
        __syncthreads();
    }
    boff[t] = (t == 0) ? 0 : s[t - 1];
    if (t == 255) rowp[n] = s[255];
}

// block-local Hillis-Steele + block offset; also re-zeroes degi for next run
// (device globals zero-init at load => run-invariant).
__global__ void scan_final_kernel(int* __restrict__ degi,
                                  const int* __restrict__ boff,
                                  int* __restrict__ rowp,
                                  int* __restrict__ curs,
                                  float* __restrict__ dinv, int n) {
    __shared__ int s[SCAN_CHUNK];
    int t = threadIdx.x;
    int i = blockIdx.x * SCAN_CHUNK + t;
    int d = (i < n) ? degi[i] : 0;
    s[t] = d;
    __syncthreads();
    for (int off = 1; off < SCAN_CHUNK; off <<= 1) {
        int v = (t >= off) ? s[t - off] : 0;
        __syncthreads();
        s[t] += v;
        __syncthreads();
    }
    if (i < n) {
        int excl = s[t] - d + boff[blockIdx.x];
        rowp[i] = excl;
        curs[i] = excl;
        dinv[i] = 1.0f / fmaxf((float)d, 1.0f);
        degi[i] = 0;
    }
}

__global__ void scatter_kernel(const int* __restrict__ ei, int E, int nnodes,
                               int* __restrict__ curs,
                               int* __restrict__ csr) {
    int e = blockIdx.x * blockDim.x + threadIdx.x;
    if (e >= E) return;
    int src = __ldg(&ei[e]);
    int dst = __ldg(&ei[E + e]);
    if ((unsigned)src >= (unsigned)nnodes || (unsigned)dst >= (unsigned)nnodes) return;
    int pos = atomicAdd(&curs[dst], 1);
    csr[pos] = src;
}

// Gather-reduce mean aggregation, 4-way unroll.
template <int F4>
__global__ void gather_agg_kernel(const float4* __restrict__ in4,
                                  const int* __restrict__ rowp,
                                  const int* __restrict__ csr,
                                  const float* __restrict__ dinv,
                                  float4* __restrict__ aggout,
                                  int n) {
    constexpr int GPB = 256 / F4;
    const int node = blockIdx.x * GPB + (threadIdx.x / F4);
    const int lane = threadIdx.x & (F4 - 1);
    if (node >= n) return;

    const int beg = __ldg(&rowp[node]);
    const int end = __ldg(&rowp[node + 1]);

    float4 a0 = make_float4(0.f, 0.f, 0.f, 0.f);
    float4 a1 = make_float4(0.f, 0.f, 0.f, 0.f);
    float4 a2 = make_float4(0.f, 0.f, 0.f, 0.f);
    float4 a3 = make_float4(0.f, 0.f, 0.f, 0.f);

    int j = beg;
    for (; j + 4 <= end; j += 4) {
        int s0 = __ldg(&csr[j]);
        int s1 = __ldg(&csr[j + 1]);
        int s2 = __ldg(&csr[j + 2]);
        int s3 = __ldg(&csr[j + 3]);
        float4 v0 = __ldg(&in4[(size_t)s0 * F4 + lane]);
        float4 v1 = __ldg(&in4[(size_t)s1 * F4 + lane]);
        float4 v2 = __ldg(&in4[(size_t)s2 * F4 + lane]);
        float4 v3 = __ldg(&in4[(size_t)s3 * F4 + lane]);
        a0.x += v0.x; a0.y += v0.y; a0.z += v0.z; a0.w += v0.w;
        a1.x += v1.x; a1.y += v1.y; a1.z += v1.z; a1.w += v1.w;
        a2.x += v2.x; a2.y += v2.y; a2.z += v2.z; a2.w += v2.w;
        a3.x += v3.x; a3.y += v3.y; a3.z += v3.z; a3.w += v3.w;
    }
    for (; j < end; j++) {
        int s0 = __ldg(&csr[j]);
        float4 v0 = __ldg(&in4[(size_t)s0 * F4 + lane]);
        a0.x += v0.x; a0.y += v0.y; a0.z += v0.z; a0.w += v0.w;
    }

    const float di = __ldg(&dinv[node]);
    float4 r;
    r.x = (a0.x + a1.x + a2.x + a3.x) * di;
    r.y = (a0.y + a1.y + a2.y + a3.y) * di;
    r.z = (a0.z + a1.z + a2.z + a3.z) * di;
    r.w = (a0.w + a1.w + a2.w + a3.w) * di;
    aggout[(size_t)node * F4 + lane] = r;
}

// Fused dense layer, f32x2 accumulators, float4 activation reads (k-step-4).
template <int K, bool RELU>
__global__ void __launch_bounds__(256)
dense_kernel(const float* __restrict__ xin,
             const float* __restrict__ agg,
             const float* __restrict__ WcT,
             const float* __restrict__ bias,
             float* __restrict__ out,
             int nnodes) {
    constexpr int K2 = 2 * K;
    extern __shared__ float sm[];
    float* sW = sm;                 // K2*128, layout [k][j]
    float* sC = sm + K2 * 128;      // 64 nodes * K2, layout [n][k]
    __shared__ float sB[128];

    const int tid  = threadIdx.x;
    const int base = blockIdx.x * 64;

    if (tid < 128) sB[tid] = bias[tid];
    {
        float4*       dst4 = reinterpret_cast<float4*>(sW);
        const float4* src4 = reinterpret_cast<const float4*>(WcT);
        for (int i = tid; i < K2 * 32; i += 256) dst4[i] = src4[i];
    }
    {
        constexpr int KQ = K / 4;
        const float4* x4 = reinterpret_cast<const float4*>(xin);
        const float4* a4 = reinterpret_cast<const float4*>(agg);
        float4 z = make_float4(0.f, 0.f, 0.f, 0.f);
        for (int i = tid; i < 64 * KQ; i += 256) {
            int n  = i / KQ;
            int kq = i - n * KQ;
            int node = base + n;
            float4 xv = z, av = z;
            if (node < nnodes) {
                size_t off = (size_t)node * KQ + kq;
                xv = x4[off];
                av = a4[off];
            }
            reinterpret_cast<float4*>(sC + n * K2)[kq]     = av;
            reinterpret_cast<float4*>(sC + n * K2 + K)[kq] = xv;
        }
    }
    __syncthreads();

    const int w = tid >> 5;
    const int l = tid & 31;

    unsigned long long acc01[8], acc23[8];
    {
        unsigned long long b01 = pk2(sB[4 * l], sB[4 * l + 1]);
        unsigned long long b23 = pk2(sB[4 * l + 2], sB[4 * l + 3]);
#pragma unroll
        for (int m = 0; m < 8; m++) { acc01[m] = b01; acc23[m] = b23; }
    }

    const float4* sW4 = reinterpret_cast<const float4*>(sW);
    const float4* sC4 = reinterpret_cast<const float4*>(sC + (w * 8) * K2);

#pragma unroll 2
    for (int k4 = 0; k4 < K2 / 4; k4++) {
        unsigned long long wp[4][2];
#pragma unroll
        for (int kk = 0; kk < 4; kk++) {
            float4 wv = sW4[(4 * k4 + kk) * 32 + l];
            wp[kk][0] = pk2(wv.x, wv.y);
            wp[kk][1] = pk2(wv.z, wv.w);
        }
#pragma unroll
        for (int m = 0; m < 8; m++) {
            float4 c4 = sC4[m * (K2 / 4) + k4];
            unsigned long long cc;
            cc = pk2(c4.x, c4.x); fma2(acc01[m], cc, wp[0][0]); fma2(acc23[m], cc, wp[0][1]);
            cc = pk2(c4.y, c4.y); fma2(acc01[m], cc, wp[1][0]); fma2(acc23[m], cc, wp[1][1]);
            cc = pk2(c4.z, c4.z); fma2(acc01[m], cc, wp[2][0]); fma2(acc23[m], cc, wp[2][1]);
            cc = pk2(c4.w, c4.w); fma2(acc01[m], cc, wp[3][0]); fma2(acc23[m], cc, wp[3][1]);
        }
    }

#pragma unroll
    for (int m = 0; m < 8; m++) {
        int node = base + w * 8 + m;
        if (node >= nnodes) continue;
        float2 p01 = upk2(acc01[m]);
        float2 p23 = upk2(acc23[m]);
        float4 o;
        o.x = p01.x; o.y = p01.y; o.z = p23.x; o.w = p23.y;
        if (RELU) {
            o.x = fmaxf(o.x, 0.f); o.y = fmaxf(o.y, 0.f);
            o.z = fmaxf(o.z, 0.f); o.w = fmaxf(o.w, 0.f);
        }
        reinterpret_cast<float4*>(out)[(size_t)node * 32 + l] = o;
    }
}

// ---------------------------------------------------------------------------
extern "C" void kernel_launch(void* const* d_in, const int* in_sizes, int n_in,
                              void* d_out, int out_size) {
    const float* x    = (const float*)d_in[0];
    const int*   ei   = (const int*)d_in[1];
    const float* W1_l = (const float*)d_in[2];
    const float* b1   = (const float*)d_in[3];
    const float* W1_r = (const float*)d_in[4];
    const float* W2_l = (const float*)d_in[5];
    const float* b2   = (const float*)d_in[6];
    const float* W2_r = (const float*)d_in[7];
    float*       out  = (float*)d_out;

    const int n = in_sizes[0] / F_IN;   // 100000
    const int E = in_sizes[1] / 2;      // 1600000
    const int nblk = (n + SCAN_CHUNK - 1) / SCAN_CHUNK;

    void *p_agg1, *p_h, *p_agg2, *p_dinv, *p_degi, *p_rowp, *p_curs, *p_csr,
         *p_bsum, *p_boff, *p_w1t, *p_w2t;
    cudaGetSymbolAddress(&p_agg1, g_agg1);
    cudaGetSymbolAddress(&p_h,    g_h);
    cudaGetSymbolAddress(&p_agg2, g_agg2);
    cudaGetSymbolAddress(&p_dinv, g_dinv);
    cudaGetSymbolAddress(&p_degi, g_degi);
    cudaGetSymbolAddress(&p_rowp, g_rowp);
    cudaGetSymbolAddress(&p_curs, g_curs);
    cudaGetSymbolAddress(&p_csr,  g_csr);
    cudaGetSymbolAddress(&p_bsum, g_bsum);
    cudaGetSymbolAddress(&p_boff, g_boff);
    cudaGetSymbolAddress(&p_w1t,  g_w1t);
    cudaGetSymbolAddress(&p_w2t,  g_w2t);
    float* agg1 = (float*)p_agg1;
    float* h    = (float*)p_h;
    float* agg2 = (float*)p_agg2;
    float* dinv = (float*)p_dinv;
    int*   degi = (int*)p_degi;
    int*   rowp = (int*)p_rowp;
    int*   curs = (int*)p_curs;
    int*   csr  = (int*)p_csr;
    int*   bsum = (int*)p_bsum;
    int*   boff = (int*)p_boff;
    float* w1t  = (float*)p_w1t;
    float* w2t  = (float*)p_w2t;

    const int smem1 = (2 * F_IN * 128 + 64 * 2 * F_IN) * (int)sizeof(float); //  96KB
    const int smem2 = (2 * F_H  * 128 + 64 * 2 * F_H ) * (int)sizeof(float); // 192KB
    cudaFuncSetAttribute(dense_kernel<F_IN, true>,
                         cudaFuncAttributeMaxDynamicSharedMemorySize, smem1);
    cudaFuncSetAttribute(dense_kernel<F_H, false>,
                         cudaFuncAttributeMaxDynamicSharedMemorySize, smem2);

    // CSR build (degi zero: zero-init at load, re-zeroed by scan_final)
    hist_kernel<<<(E + 255) / 256, 256>>>(ei, E, n, degi);
    scan_partial_kernel<<<nblk, SCAN_CHUNK>>>(degi, bsum, n);
    scan_bsum_kernel<<<1, 256>>>(bsum, boff, rowp, nblk, n);
    scan_final_kernel<<<nblk, SCAN_CHUNK>>>(degi, boff, rowp, curs, dinv, n);
    scatter_kernel<<<(E + 255) / 256, 256>>>(ei, E, n, curs, csr);

    // layer 1
    gather_agg_kernel<F_IN / 4><<<(n * (F_IN / 4) + 255) / 256, 256>>>(
        (const float4*)x, rowp, csr, dinv, (float4*)agg1, n);
    pack_all_kernel<<<(2 * F_H * 128 + 255) / 256, 256>>>(
        W1_l, W1_r, W2_l, W2_r, w1t, w2t);
    dense_kernel<F_IN, true><<<(n + 63) / 64, 256, smem1>>>(
        x, agg1, w1t, b1, h, n);

    // layer 2
    gather_agg_kernel<F_H / 4><<<(n * (F_H / 4) + 255) / 256, 256>>>(
        (const float4*)h, rowp, csr, dinv, (float4*)agg2, n);
    dense_kernel<F_H, false><<<(n + 63) / 64, 256, smem2>>>(
        h, agg2, w2t, b2, out, n);
}

// round 8
// speedup vs baseline: 1.9896x; 1.1531x over previous
#include <cuda_runtime.h>
#include <cuda_bf16.h>
#include <cstdint>

// ---------------------------------------------------------------------------
// GraphSAGE 2-layer backbone, CSR gather-reduce + f32x2 packed dense.
// R8: dense weights read via __ldg (L1-resident, shared across CTAs) instead of
//     smem staging -> smem/CTA drops 192KB->64KB (dense2), occupancy 1->3 CTA/SM.
// ---------------------------------------------------------------------------

static constexpr int NN   = 100000;
static constexpr int EE   = 1600000;
static constexpr int F_IN = 64;
static constexpr int F_H  = 128;
static constexpr int SCAN_CHUNK = 512;

__device__ __align__(16) float g_agg1 [(size_t)NN * F_IN];
__device__ __align__(16) float g_h    [(size_t)NN * F_H];
__device__ __align__(16) float g_agg2 [(size_t)NN * F_H];
__device__ __align__(16) float g_dinv [NN];
__device__ __align__(16) int   g_degi [NN];      // zero at load; final re-zeroes
__device__ __align__(16) int   g_rowp [NN + 1];
__device__ __align__(16) int   g_curs [NN];
__device__ __align__(16) int   g_csr  [EE];
__device__ __align__(16) int   g_bsum [256];
__device__ __align__(16) int   g_boff [256];
__device__ __align__(16) float g_w1t  [2 * F_IN * 128];
__device__ __align__(16) float g_w2t  [2 * F_H  * 128];

// ---------------------------------------------------------------------------
__device__ __forceinline__ unsigned long long pk2(float a, float b) {
    unsigned long long r;
    asm("mov.b64 %0, {%1, %2};" : "=l"(r) : "f"(a), "f"(b));
    return r;
}
__device__ __forceinline__ void fma2(unsigned long long& d,
                                     unsigned long long a,
                                     unsigned long long b) {
    asm("fma.rn.f32x2 %0, %1, %2, %0;" : "+l"(d) : "l"(a), "l"(b));
}
__device__ __forceinline__ float2 upk2(unsigned long long v) {
    float2 f;
    asm("mov.b64 {%0, %1}, %2;" : "=f"(f.x), "=f"(f.y) : "l"(v));
    return f;
}

// ---------------------------------------------------------------------------
__global__ void pack_all_kernel(const float* __restrict__ W1l,
                                const float* __restrict__ W1r,
                                const float* __restrict__ W2l,
                                const float* __restrict__ W2r,
                                float* __restrict__ w1t,
                                float* __restrict__ w2t) {
    int i = blockIdx.x * blockDim.x + threadIdx.x;
    if (i < 2 * F_IN * 128) {
        int k = i >> 7, j = i & 127;
        w1t[i] = (k < F_IN) ? W1l[j * F_IN + k] : W1r[j * F_IN + (k - F_IN)];
    }
    if (i < 2 * F_H * 128) {
        int k = i >> 7, j = i & 127;
        w2t[i] = (k < F_H) ? W2l[j * F_H + k] : W2r[j * F_H + (k - F_H)];
    }
}

__global__ void hist_kernel(const int* __restrict__ ei, int E, int nnodes,
                            int* __restrict__ degi) {
    int e = blockIdx.x * blockDim.x + threadIdx.x;
    if (e >= E) return;
    int dst = __ldg(&ei[E + e]);
    if ((unsigned)dst < (unsigned)nnodes) atomicAdd(&degi[dst], 1);
}

// ---- coalesced 3-pass exclusive scan over degi ----
__global__ void scan_partial_kernel(const int* __restrict__ degi,
                                    int* __restrict__ bsum, int n) {
    __shared__ int s[SCAN_CHUNK];
    int t = threadIdx.x;
    int i = blockIdx.x * SCAN_CHUNK + t;
    s[t] = (i < n) ? degi[i] : 0;
    __syncthreads();
    for (int off = SCAN_CHUNK / 2; off > 0; off >>= 1) {
        if (t < off) s[t] += s[t + off];
        __syncthreads();
    }
    if (t == 0) bsum[blockIdx.x] = s[0];
}

__global__ void scan_bsum_kernel(const int* __restrict__ bsum,
                                 int* __restrict__ boff,
                                 int* __restrict__ rowp,
                                 int nblk, int n) {
    __shared__ int s[256];
    int t = threadIdx.x;
    s[t] = (t < nblk) ? bsum[t] : 0;
    __syncthreads();
    for (int off = 1; off < 256; off <<= 1) {
        int v = (t >= off) ? s[t - off] : 0;
        __syncthreads();
        s[t] += v;
        __syncthreads();
    }
    boff[t] = (t == 0) ? 0 : s[t - 1];
    if (t == 255) rowp[n] = s[255];
}

__global__ void scan_final_kernel(int* __restrict__ degi,
                                  const int* __restrict__ boff,
                                  int* __restrict__ rowp,
                                  int* __restrict__ curs,
                                  float* __restrict__ dinv, int n) {
    __shared__ int s[SCAN_CHUNK];
    int t = threadIdx.x;
    int i = blockIdx.x * SCAN_CHUNK + t;
    int d = (i < n) ? degi[i] : 0;
    s[t] = d;
    __syncthreads();
    for (int off = 1; off < SCAN_CHUNK; off <<= 1) {
        int v = (t >= off) ? s[t - off] : 0;
        __syncthreads();
        s[t] += v;
        __syncthreads();
    }
    if (i < n) {
        int excl = s[t] - d + boff[blockIdx.x];
        rowp[i] = excl;
        curs[i] = excl;
        dinv[i] = 1.0f / fmaxf((float)d, 1.0f);
        degi[i] = 0;
    }
}

__global__ void scatter_kernel(const int* __restrict__ ei, int E, int nnodes,
                               int* __restrict__ curs,
                               int* __restrict__ csr) {
    int e = blockIdx.x * blockDim.x + threadIdx.x;
    if (e >= E) return;
    int src = __ldg(&ei[e]);
    int dst = __ldg(&ei[E + e]);
    if ((unsigned)src >= (unsigned)nnodes || (unsigned)dst >= (unsigned)nnodes) return;
    int pos = atomicAdd(&curs[dst], 1);
    csr[pos] = src;
}

// Gather-reduce mean aggregation, 4-way unroll.
template <int F4>
__global__ void gather_agg_kernel(const float4* __restrict__ in4,
                                  const int* __restrict__ rowp,
                                  const int* __restrict__ csr,
                                  const float* __restrict__ dinv,
                                  float4* __restrict__ aggout,
                                  int n) {
    constexpr int GPB = 256 / F4;
    const int node = blockIdx.x * GPB + (threadIdx.x / F4);
    const int lane = threadIdx.x & (F4 - 1);
    if (node >= n) return;

    const int beg = __ldg(&rowp[node]);
    const int end = __ldg(&rowp[node + 1]);

    float4 a0 = make_float4(0.f, 0.f, 0.f, 0.f);
    float4 a1 = make_float4(0.f, 0.f, 0.f, 0.f);
    float4 a2 = make_float4(0.f, 0.f, 0.f, 0.f);
    float4 a3 = make_float4(0.f, 0.f, 0.f, 0.f);

    int j = beg;
    for (; j + 4 <= end; j += 4) {
        int s0 = __ldg(&csr[j]);
        int s1 = __ldg(&csr[j + 1]);
        int s2 = __ldg(&csr[j + 2]);
        int s3 = __ldg(&csr[j + 3]);
        float4 v0 = __ldg(&in4[(size_t)s0 * F4 + lane]);
        float4 v1 = __ldg(&in4[(size_t)s1 * F4 + lane]);
        float4 v2 = __ldg(&in4[(size_t)s2 * F4 + lane]);
        float4 v3 = __ldg(&in4[(size_t)s3 * F4 + lane]);
        a0.x += v0.x; a0.y += v0.y; a0.z += v0.z; a0.w += v0.w;
        a1.x += v1.x; a1.y += v1.y; a1.z += v1.z; a1.w += v1.w;
        a2.x += v2.x; a2.y += v2.y; a2.z += v2.z; a2.w += v2.w;
        a3.x += v3.x; a3.y += v3.y; a3.z += v3.z; a3.w += v3.w;
    }
    for (; j < end; j++) {
        int s0 = __ldg(&csr[j]);
        float4 v0 = __ldg(&in4[(size_t)s0 * F4 + lane]);
        a0.x += v0.x; a0.y += v0.y; a0.z += v0.z; a0.w += v0.w;
    }

    const float di = __ldg(&dinv[node]);
    float4 r;
    r.x = (a0.x + a1.x + a2.x + a3.x) * di;
    r.y = (a0.y + a1.y + a2.y + a3.y) * di;
    r.z = (a0.z + a1.z + a2.z + a3.z) * di;
    r.w = (a0.w + a1.w + a2.w + a3.w) * di;
    aggout[(size_t)node * F4 + lane] = r;
}

// Fused dense layer, f32x2 accumulators, float4 activation reads.
// Weights read via __ldg (shared across all CTAs -> L1/L2 resident);
// only the 64-node activation tile lives in smem (32KB K=64 / 64KB K=128).
template <int K, bool RELU>
__global__ void __launch_bounds__(256)
dense_kernel(const float* __restrict__ xin,
             const float* __restrict__ agg,
             const float* __restrict__ WcT,
             const float* __restrict__ bias,
             float* __restrict__ out,
             int nnodes) {
    constexpr int K2 = 2 * K;
    extern __shared__ float sm[];
    float* sC = sm;                 // 64 nodes * K2, layout [n][k]
    __shared__ float sB[128];

    const int tid  = threadIdx.x;
    const int base = blockIdx.x * 64;

    if (tid < 128) sB[tid] = bias[tid];
    {
        constexpr int KQ = K / 4;
        const float4* x4 = reinterpret_cast<const float4*>(xin);
        const float4* a4 = reinterpret_cast<const float4*>(agg);
        float4 z = make_float4(0.f, 0.f, 0.f, 0.f);
        for (int i = tid; i < 64 * KQ; i += 256) {
            int n  = i / KQ;
            int kq = i - n * KQ;
            int node = base + n;
            float4 xv = z, av = z;
            if (node < nnodes) {
                size_t off = (size_t)node * KQ + kq;
                xv = x4[off];
                av = a4[off];
            }
            reinterpret_cast<float4*>(sC + n * K2)[kq]     = av;
            reinterpret_cast<float4*>(sC + n * K2 + K)[kq] = xv;
        }
    }
    __syncthreads();

    const int w = tid >> 5;
    const int l = tid & 31;

    unsigned long long acc01[8], acc23[8];
    {
        unsigned long long b01 = pk2(sB[4 * l], sB[4 * l + 1]);
        unsigned long long b23 = pk2(sB[4 * l + 2], sB[4 * l + 3]);
#pragma unroll
        for (int m = 0; m < 8; m++) { acc01[m] = b01; acc23[m] = b23; }
    }

    const float4* W4  = reinterpret_cast<const float4*>(WcT);
    const float4* sC4 = reinterpret_cast<const float4*>(sC + (w * 8) * K2);

#pragma unroll 2
    for (int k4 = 0; k4 < K2 / 4; k4++) {
        unsigned long long wp[4][2];
#pragma unroll
        for (int kk = 0; kk < 4; kk++) {
            float4 wv = __ldg(&W4[(4 * k4 + kk) * 32 + l]);   // L1-hot LDG.128
            wp[kk][0] = pk2(wv.x, wv.y);
            wp[kk][1] = pk2(wv.z, wv.w);
        }
#pragma unroll
        for (int m = 0; m < 8; m++) {
            float4 c4 = sC4[m * (K2 / 4) + k4];                // broadcast LDS.128
            unsigned long long cc;
            cc = pk2(c4.x, c4.x); fma2(acc01[m], cc, wp[0][0]); fma2(acc23[m], cc, wp[0][1]);
            cc = pk2(c4.y, c4.y); fma2(acc01[m], cc, wp[1][0]); fma2(acc23[m], cc, wp[1][1]);
            cc = pk2(c4.z, c4.z); fma2(acc01[m], cc, wp[2][0]); fma2(acc23[m], cc, wp[2][1]);
            cc = pk2(c4.w, c4.w); fma2(acc01[m], cc, wp[3][0]); fma2(acc23[m], cc, wp[3][1]);
        }
    }

#pragma unroll
    for (int m = 0; m < 8; m++) {
        int node = base + w * 8 + m;
        if (node >= nnodes) continue;
        float2 p01 = upk2(acc01[m]);
        float2 p23 = upk2(acc23[m]);
        float4 o;
        o.x = p01.x; o.y = p01.y; o.z = p23.x; o.w = p23.y;
        if (RELU) {
            o.x = fmaxf(o.x, 0.f); o.y = fmaxf(o.y, 0.f);
            o.z = fmaxf(o.z, 0.f); o.w = fmaxf(o.w, 0.f);
        }
        reinterpret_cast<float4*>(out)[(size_t)node * 32 + l] = o;
    }
}

// ---------------------------------------------------------------------------
extern "C" void kernel_launch(void* const* d_in, const int* in_sizes, int n_in,
                              void* d_out, int out_size) {
    const float* x    = (const float*)d_in[0];
    const int*   ei   = (const int*)d_in[1];
    const float* W1_l = (const float*)d_in[2];
    const float* b1   = (const float*)d_in[3];
    const float* W1_r = (const float*)d_in[4];
    const float* W2_l = (const float*)d_in[5];
    const float* b2   = (const float*)d_in[6];
    const float* W2_r = (const float*)d_in[7];
    float*       out  = (float*)d_out;

    const int n = in_sizes[0] / F_IN;   // 100000
    const int E = in_sizes[1] / 2;      // 1600000
    const int nblk = (n + SCAN_CHUNK - 1) / SCAN_CHUNK;

    void *p_agg1, *p_h, *p_agg2, *p_dinv, *p_degi, *p_rowp, *p_curs, *p_csr,
         *p_bsum, *p_boff, *p_w1t, *p_w2t;
    cudaGetSymbolAddress(&p_agg1, g_agg1);
    cudaGetSymbolAddress(&p_h,    g_h);
    cudaGetSymbolAddress(&p_agg2, g_agg2);
    cudaGetSymbolAddress(&p_dinv, g_dinv);
    cudaGetSymbolAddress(&p_degi, g_degi);
    cudaGetSymbolAddress(&p_rowp, g_rowp);
    cudaGetSymbolAddress(&p_curs, g_curs);
    cudaGetSymbolAddress(&p_csr,  g_csr);
    cudaGetSymbolAddress(&p_bsum, g_bsum);
    cudaGetSymbolAddress(&p_boff, g_boff);
    cudaGetSymbolAddress(&p_w1t,  g_w1t);
    cudaGetSymbolAddress(&p_w2t,  g_w2t);
    float* agg1 = (float*)p_agg1;
    float* h    = (float*)p_h;
    float* agg2 = (float*)p_agg2;
    float* dinv = (float*)p_dinv;
    int*   degi = (int*)p_degi;
    int*   rowp = (int*)p_rowp;
    int*   curs = (int*)p_curs;
    int*   csr  = (int*)p_csr;
    int*   bsum = (int*)p_bsum;
    int*   boff = (int*)p_boff;
    float* w1t  = (float*)p_w1t;
    float* w2t  = (float*)p_w2t;

    const int smem1 = 64 * 2 * F_IN * (int)sizeof(float); // 32KB
    const int smem2 = 64 * 2 * F_H  * (int)sizeof(float); // 64KB
    cudaFuncSetAttribute(dense_kernel<F_IN, true>,
                         cudaFuncAttributeMaxDynamicSharedMemorySize, smem1);
    cudaFuncSetAttribute(dense_kernel<F_H, false>,
                         cudaFuncAttributeMaxDynamicSharedMemorySize, smem2);

    // CSR build (degi zero: zero-init at load, re-zeroed by scan_final)
    hist_kernel<<<(E + 255) / 256, 256>>>(ei, E, n, degi);
    scan_partial_kernel<<<nblk, SCAN_CHUNK>>>(degi, bsum, n);
    scan_bsum_kernel<<<1, 256>>>(bsum, boff, rowp, nblk, n);
    scan_final_kernel<<<nblk, SCAN_CHUNK>>>(degi, boff, rowp, curs, dinv, n);
    scatter_kernel<<<(E + 255) / 256, 256>>>(ei, E, n, curs, csr);

    // layer 1
    gather_agg_kernel<F_IN / 4><<<(n * (F_IN / 4) + 255) / 256, 256>>>(
        (const float4*)x, rowp, csr, dinv, (float4*)agg1, n);
    pack_all_kernel<<<(2 * F_H * 128 + 255) / 256, 256>>>(
        W1_l, W1_r, W2_l, W2_r, w1t, w2t);
    dense_kernel<F_IN, true><<<(n + 63) / 64, 256, smem1>>>(
        x, agg1, w1t, b1, h, n);

    // layer 2
    gather_agg_kernel<F_H / 4><<<(n * (F_H / 4) + 255) / 256, 256>>>(
        (const float4*)h, rowp, csr, dinv, (float4*)agg2, n);
    dense_kernel<F_H, false><<<(n + 63) / 64, 256, smem2>>>(
        h, agg2, w2t, b2, out, n);
}